// round 13
// baseline (speedup 1.0000x reference)
#include <cuda_runtime.h>
#include <cuda_fp16.h>
#include <cstdint>

// ConvNearestNeightbor: out[b, n*C+c, h, w] = max_k |x_pad[b,c,h-row,w-col] - nb[n,c,k]|
// R13: no resource saturated (fma<=32, alu<=52, L1~47, issue<=70) -> amortize overhead.
// 8 outputs/thread (4 half2 lanes), warps 0-3 / 4-7 split the 16 n-planes -> neighbor
// LDS + loop + pointer overhead halved per output. Math stays at 3-op/tap floor,
// pipe-balanced: HSUB2(fma) + LOP3-abs(alu) + HMNMX(fma)/VIMNMX(alu) trees.

namespace {

constexpr int B = 16, C = 32, H = 32, W = 32, NUM = 32;
constexpr int HW = H * W;
constexpr int NSPLIT = 2;
constexpr int NPER = NUM / NSPLIT;   // 16 planes per block
constexpr int NHALF = NPER / 2;      // 8 planes per warp-group

__device__ __forceinline__ uint32_t h2bits(__half2 v) { return *reinterpret_cast<uint32_t*>(&v); }
__device__ __forceinline__ __half2 bits2h(uint32_t v) { return *reinterpret_cast<__half2*>(&v); }
__device__ __forceinline__ uint32_t habs_bits(__half2 d) { return h2bits(d) & 0x7FFF7FFFu; }
__device__ __forceinline__ uint32_t umax2(uint32_t a, uint32_t b) {
  uint32_t r;
  asm("max.u16x2 %0, %1, %2;" : "=r"(r) : "r"(a), "r"(b));
  return r;
}
__device__ __forceinline__ uint32_t hmax2b(uint32_t a, uint32_t b) {
  __half2 r = __hmax2(bits2h(a), bits2h(b));
  return h2bits(r);
}

__global__ __launch_bounds__(256, 6) void cnn_kernel(
    const float* __restrict__ x,
    const float* __restrict__ nb,
    float* __restrict__ out) {
  __shared__ __align__(16) __half xs[34 * 36];     // fp16 halo tile
  __shared__ __align__(16) __half2 nbs[NPER][16];  // duplicated {n,n}, padded rows

  const int bc = blockIdx.x;   // 0 .. B*C-1
  const int ns = blockIdx.y;   // 0 .. NSPLIT-1
  const int c  = bc & (C - 1);
  const int b  = bc / C;
  const int tid = threadIdx.x;

  // ---- neighbors (all 16 planes of this split), duplicated into half2 ----
  if (tid < NPER * 9) {
    int nn = tid / 9;
    int k  = tid - nn * 9;
    float v = nb[(size_t)(ns * NPER + nn) * (C * 9) + c * 9 + k];
    nbs[nn][k] = __float2half2_rn(v);
  }

  // ---- x tile: 1 vector LDG per thread -> fp16, + predicated halo zeros ----
  const float* xp = x + (size_t)bc * HW;
  {
    const int lh = tid >> 3;            // 0..31
    const int lw = (tid & 7) << 2;      // 0,4,...,28
    float4 v = *(const float4*)(xp + lh * W + lw);
    __half* dst = &xs[(lh + 1) * 36 + lw + 1];
    dst[0] = __float2half_rn(v.x);
    dst[1] = __float2half_rn(v.y);
    dst[2] = __float2half_rn(v.z);
    dst[3] = __float2half_rn(v.w);
  }
  if (tid < 132) {  // halo: rows 0,33 cols 0..33; cols 0,33 rows 1..32
    int rr, cc;
    if (tid < 68)        { rr = (tid < 34) ? 0 : 33; cc = (tid < 34) ? tid : tid - 34; }
    else if (tid < 100)  { rr = tid - 68 + 1;  cc = 0; }
    else                 { rr = tid - 100 + 1; cc = 33; }
    *(unsigned short*)&xs[rr * 36 + cc] = 0;
  }
  __syncthreads();

  // ---- compute geometry: warp-group splits planes; thread = row h, 8 cols ----
  const int grp  = tid >> 7;            // 0 or 1 -> planes grp*8 .. grp*8+7
  const int wtid = tid & 127;
  const int h  = wtid >> 2;             // 0..31
  const int wq = (wtid & 3) << 3;       // 0,8,16,24

  // window: rows h..h+2 of padded tile, cols wq..wq+9 (10 halves)
  // A[r][i] = {col wq+2i, wq+2i+1} i=0..4 ; S[r][i] = {col wq+2i+1, wq+2i+2} i=0..3
  uint32_t A[3][5], S[3][4];
#pragma unroll
  for (int r = 0; r < 3; r++) {
    const __half* base = &xs[(h + r) * 36 + wq];
    uint2 v01 = *(const uint2*)(base);        // A0, A1  (8B-aligned)
    uint2 v23 = *(const uint2*)(base + 4);    // A2, A3
    uint32_t v4 = *(const uint32_t*)(base + 8);
    A[r][0] = v01.x; A[r][1] = v01.y;
    A[r][2] = v23.x; A[r][3] = v23.y;
    A[r][4] = v4;
#pragma unroll
    for (int i = 0; i < 4; i++) {
      __half2 s = __halves2half2(__high2half(bits2h(A[r][i])),
                                 __low2half(bits2h(A[r][i + 1])));
      S[r][i] = h2bits(s);
    }
  }

  float* const outp =
      out + ((size_t)(b * NUM + ns * NPER + grp * NHALF) * C + c) * HW + h * W + wq;

#pragma unroll
  for (int nn = 0; nn < NHALF; nn++) {
    const int plane = grp * NHALF + nn;
    uint32_t nv[9];
    {
      uint4 c0 = *(const uint4*)&nbs[plane][0];   // k0..k3
      uint4 c1 = *(const uint4*)&nbs[plane][4];   // k4..k7
      nv[0] = c0.x; nv[1] = c0.y; nv[2] = c0.z; nv[3] = c0.w;
      nv[4] = c1.x; nv[5] = c1.y; nv[6] = c1.z; nv[7] = c1.w;
      nv[8] = h2bits(nbs[plane][8]);
    }

    float4 o0, o1;
#pragma unroll
    for (int p = 0; p < 4; p++) {  // output pair p -> cols (wq+2p, wq+2p+1)
      uint32_t a[9];
#pragma unroll
      for (int k = 0; k < 9; k++) {
        const int r  = 2 - k / 3;
        const int cc = 2 - k % 3;              // 0 -> A[p], 1 -> S[p], 2 -> A[p+1]
        uint32_t xvv = (cc == 0) ? A[r][p] : (cc == 1) ? S[r][p] : A[r][p + 1];
        a[k] = habs_bits(__hsub2(bits2h(xvv), bits2h(nv[k])));  // HSUB2(fma)+LOP3(alu)
      }
      uint32_t hf = hmax2b(hmax2b(a[0], a[1]), hmax2b(a[2], a[3]));  // 3x fma
      uint32_t uu = umax2(umax2(a[4], a[5]), umax2(a[6], a[7]));     // 3x alu
      uu = umax2(uu, a[8]);                                          // alu
      uint32_t m = umax2(uu, hf);                                    // alu
      float2 f = __half22float2(bits2h(m));
      if (p == 0)      { o0.x = f.x; o0.y = f.y; }
      else if (p == 1) { o0.z = f.x; o0.w = f.y; }
      else if (p == 2) { o1.x = f.x; o1.y = f.y; }
      else             { o1.z = f.x; o1.w = f.y; }
    }
    float* dst = outp + (size_t)nn * C * HW;
    *(float4*)dst       = o0;
    *(float4*)(dst + 4) = o1;
  }
}

}  // namespace

extern "C" void kernel_launch(void* const* d_in, const int* in_sizes, int n_in,
                              void* d_out, int out_size) {
  const float* x  = (const float*)d_in[0];   // (B,C,H,W) fp32
  const float* nb = (const float*)d_in[1];   // (NUM,C,9) fp32
  float* out = (float*)d_out;                // (B, NUM*C, H, W) fp32
  dim3 grid(B * C, NSPLIT);
  cnn_kernel<<<grid, 256>>>(x, nb, out);
}